// round 16
// baseline (speedup 1.0000x reference)
#include <cuda_runtime.h>
#include <cuda_fp16.h>
#include <cstdint>

#define BB 4
#define CC 256
#define OO 256
#define HWW 4096
#define NN 16384          // BB*HWW
#define CKK 2304          // CC*9 — plain fp16 K
#define EPSB 1e-5f
#define FNN 16384.0f

#define NSTAGE 4
#define STAGE_SZ 49152      // A 16KB + B 32KB per stage (main GEMM)
#define GEMM_SMEM (NSTAGE * STAGE_SZ)      // 192 KB
#define NUM_KCH 36          // CKK*2 bytes / 128B per chunk

#define OFF_STAGE 12288     // A 4KB (32 rows) + B 8KB (64 rows)
#define OFF_SMEM (NSTAGE * OFF_STAGE)      // 48 KB

#define COLROW 2304         // per pixel: 9 kpt x 256 fp16
#define O1ROW 256           // per pixel: 256 fp16

// ---------------- scratch (device globals; no allocs allowed) ----------------
__device__ float g_offset[BB * 18 * HWW];                       // 4.7 MB
__device__ __half g_xpm[(size_t)NN * CC];                       // 8.4 MB NHWC fp16 x
__device__ __half g_colb[(size_t)NN * COLROW];                  // 75.5 MB
__device__ __half g_wA1[(size_t)OO * CKK];                      // 1.2 MB [m][k]
__device__ __half g_wA2[(size_t)OO * CKK];
__device__ __half g_wOff[32 * CKK];                             // 147 KB (18 pad 32)
__device__ float g_out1[(size_t)OO * NN];                       // 16.8 MB [o][n]
__device__ float g_out2[(size_t)OO * NN];
__device__ __half g_out1b[(size_t)NN * O1ROW];                  // 8.4 MB
__device__ float g_scale1[OO], g_shift1[OO], g_scale2[OO], g_shift2[OO];
__device__ float g_bnsum1[OO], g_bnsq1[OO], g_bnsum2[OO], g_bnsq2[OO];

// ---------------- helpers ----------------------------------------------------
__device__ __forceinline__ uint32_t smem_u32(const void* p) {
    uint32_t a;
    asm("{ .reg .u64 t; cvta.to.shared.u64 t, %1; cvt.u32.u64 %0, t; }" : "=r"(a) : "l"(p));
    return a;
}
#define SWZ128(o) ((o) ^ (((o) >> 3) & 0x70))
#define CP_ASYNC16(dst, src) \
    asm volatile("cp.async.cg.shared.global [%0], [%1], 16;" :: "r"(dst), "l"(src))
#define CP_ASYNC16Z(dst, src, sz) \
    asm volatile("cp.async.cg.shared.global [%0], [%1], 16, %2;" :: "r"(dst), "l"(src), "r"(sz))
#define CP_COMMIT() asm volatile("cp.async.commit_group;" ::: "memory")
#define CP_WAIT2()  asm volatile("cp.async.wait_group 2;" ::: "memory")

#define LDSM4(r0, r1, r2, r3, addr) \
    asm volatile("ldmatrix.sync.aligned.m8n8.x4.shared.b16 {%0,%1,%2,%3}, [%4];" \
                 : "=r"(r0), "=r"(r1), "=r"(r2), "=r"(r3) : "r"(addr))

#define MMA16816F16(d, a0, a1, a2, a3, b0, b1) \
    asm volatile("mma.sync.aligned.m16n8k16.row.col.f32.f16.f16.f32 " \
                 "{%0,%1,%2,%3},{%4,%5,%6,%7},{%8,%9},{%0,%1,%2,%3};" \
                 : "+f"((d)[0]), "+f"((d)[1]), "+f"((d)[2]), "+f"((d)[3]) \
                 : "r"(a0), "r"(a1), "r"(a2), "r"(a3), "r"(b0), "r"(b1))

__device__ __forceinline__ unsigned short f2h(float v) {
    __half h = __float2half_rn(v);
    return *reinterpret_cast<unsigned short*>(&h);
}

// ---------------- zero: bn sums (1 block) ------------------------------------
__global__ void k_zero() {
    int i = threadIdx.x;
    g_bnsum1[i] = 0.f; g_bnsq1[i] = 0.f; g_bnsum2[i] = 0.f; g_bnsq2[i] = 0.f;
}

// ---------------- transpose x: NCHW fp32 -> NHWC fp16 (g_xpm) ---------------
__global__ __launch_bounds__(256)
void k_transpose_x(const float* __restrict__ x) {
    __shared__ float t[64][33];
    int n0 = blockIdx.x * 32;
    int c0 = blockIdx.y * 64;
    int b = n0 >> 12;
    int hw0 = n0 & 4095;
    int lane = threadIdx.x & 31, wy = threadIdx.x >> 5;
#pragma unroll
    for (int j = 0; j < 8; j++) {
        int cc = wy * 8 + j;
        t[cc][lane] = x[((size_t)b * CC + c0 + cc) * HWW + hw0 + lane];
    }
    __syncthreads();
#pragma unroll
    for (int j = 0; j < 4; j++) {
        int px = wy * 4 + j;
        __half2 h = __floats2half2_rn(t[lane * 2][px], t[lane * 2 + 1][px]);
        *reinterpret_cast<__half2*>(g_xpm + (size_t)(n0 + px) * CC + c0 + lane * 2) = h;
    }
}

// ---------------- weight prep v2: one block per m row, coalesced writes ------
// grid (256, 3): y selects dw/w2/off_w. For y==2 only m<32 active (m>=18 zeros).
__global__ __launch_bounds__(256)
void k_wprep(const float* __restrict__ dw, const float* __restrict__ w2,
             const float* __restrict__ off_w) {
    __shared__ float sw[CKK];
    int m = blockIdx.x;
    int y = blockIdx.y;
    if (y == 2 && m >= 32) return;
    bool zero = (y == 2 && m >= 18);
    const float* src = (y == 0) ? dw : (y == 1 ? w2 : off_w);
    __half* dst = (y == 0) ? g_wA1 : (y == 1 ? g_wA2 : g_wOff);
    int tid = threadIdx.x;
    if (!zero) {
        for (int i = tid; i < CKK; i += 256) sw[i] = src[(size_t)m * CKK + i];
    }
    __syncthreads();
    unsigned short* drow = reinterpret_cast<unsigned short*>(dst) + (size_t)m * CKK;
#pragma unroll
    for (int kpt = 0; kpt < 9; kpt++) {
        unsigned short v = zero ? (unsigned short)0 : f2h(sw[tid * 9 + kpt]);
        drow[kpt * 256 + tid] = v;
    }
}

// ---------------- offset conv as implicit fp16 GEMM: [18(32)x2304]@[2304xNN]
// grid 256: n-tile 64 pixels. 8 warps 2m x 4n, warp tile 16x16. 4-stage pipe.
__global__ __launch_bounds__(256, 3)
void k_gemm_off(const float* __restrict__ off_b) {
    extern __shared__ char smem[];
    uint32_t sb = smem_u32(smem);
    int tid = threadIdx.x;
    int n0 = blockIdx.x * 64;
    int b = n0 >> 12;

    const char* Abase = reinterpret_cast<const char*>(g_wOff);
    const char* Xbase = reinterpret_cast<const char*>(g_xpm);

    auto load_stage = [&](int kc, int s) {
        uint32_t st = sb + s * OFF_STAGE;
        int kpt = kc >> 2, part = kc & 3;
        uint32_t srcoff = ((uint32_t)part) << 7;
        int ki = kpt / 3, kj = kpt - 3 * ki;
        int dn = (ki - 1) * 128 + (kj - 1) * 2;   // dil=2 shifts
#pragma unroll
        for (int i = 0; i < 3; i++) {
            int idx = tid + i * 256;
            if (idx < 256) {
                int r = idx >> 3, c = idx & 7;
                uint32_t off = SWZ128(r * 128 + c * 16);
                CP_ASYNC16(st + off, Abase + (size_t)r * (CKK * 2) + (size_t)kc * 128 + c * 16);
            } else {
                int j = idx - 256;
                int r = j >> 3, c = j & 7;
                int n = n0 + r;
                int h = (n >> 6) & 63, w = n & 63;
                int y = h - 2 + 2 * ki, xw = w - 2 + 2 * kj;
                bool valid = ((unsigned)y < 64u) && ((unsigned)xw < 64u);
                int np = valid ? n + dn : 0;
                uint32_t sz = valid ? 16u : 0u;
                uint32_t off = SWZ128(r * 128 + c * 16);
                CP_ASYNC16Z(st + 4096 + off, Xbase + (size_t)np * 512 + srcoff + c * 16, sz);
            }
        }
        CP_COMMIT();
    };

    int lane = tid & 31, w = tid >> 5;
    int wm = w >> 2, wn = w & 3;      // 2m x 4n warp grid
    int mW = wm * 16, nW = wn * 16;
    int gq = lane >> 3, rr = lane & 7;
    int rowin = (gq & 1) * 8 + rr;
    int kboff = (gq >> 1) * 16;

    float acc[2][4];
#pragma unroll
    for (int j = 0; j < 2; j++)
#pragma unroll
        for (int q = 0; q < 4; q++) acc[j][q] = 0.f;

    uint32_t aOff = (mW + rowin) * 128;
    uint32_t aXor = ((mW + rowin) & 7) << 4;
    uint32_t bOff = (nW + rowin) * 128;
    uint32_t bXor = ((nW + rowin) & 7) << 4;

    load_stage(0, 0);
    load_stage(1, 1);
    load_stage(2, 2);

    for (int k = 0; k < NUM_KCH; k++) {
        int s = k & 3;
        uint32_t stA = sb + s * OFF_STAGE;
        uint32_t stB = stA + 4096;
        CP_WAIT2();
        __syncthreads();
        if (k + 3 < NUM_KCH) load_stage(k + 3, (k + 3) & 3);
        else CP_COMMIT();

#pragma unroll
        for (int ks = 0; ks < 4; ks++) {
            uint32_t kb = ks * 32 + kboff;
            uint32_t a0, a1, a2, a3;
            LDSM4(a0, a1, a2, a3, stA + aOff + (kb ^ aXor));
            uint32_t bf0, bf1, bf2, bf3;
            LDSM4(bf0, bf1, bf2, bf3, stB + bOff + (kb ^ bXor));
            MMA16816F16(acc[0], a0, a1, a2, a3, bf0, bf2);
            MMA16816F16(acc[1], a0, a1, a2, a3, bf1, bf3);
        }
    }

    // epilogue: rows < 18 -> g_offset[(b*18+row)*HWW + hw] (+ off_b)
    int qr = lane >> 2;
    int qc = (lane & 3) * 2;
    int hw0 = (n0 & 4095) + nW + qc;
    int rowA = mW + qr;
    int rowB = rowA + 8;
#pragma unroll
    for (int j = 0; j < 2; j++) {
        int hw = hw0 + j * 8;
        if (rowA < 18) {
            float bv = off_b[rowA];
            float2 v = make_float2(acc[j][0] + bv, acc[j][1] + bv);
            *reinterpret_cast<float2*>(g_offset + (size_t)(b * 18 + rowA) * HWW + hw) = v;
        }
        if (rowB < 18) {
            float bv = off_b[rowB];
            float2 v = make_float2(acc[j][2] + bv, acc[j][3] + bv);
            *reinterpret_cast<float2*>(g_offset + (size_t)(b * 18 + rowB) * HWW + hw) = v;
        }
    }
}

// ---------------- deformable im2col: NHWC fp16 gather -----------------------
__global__ __launch_bounds__(256)
void k_im2col_deform() {
    __shared__ float4 wts[9][32];
    __shared__ int4 idxs[9][32];

    int n0 = blockIdx.x * 32;
    int b = n0 >> 12;

    for (int t = threadIdx.x; t < 288; t += 256) {
        int kpt = t >> 5, px = t & 31;
        int n = n0 + px;
        int hw = n & 4095;
        int h = hw >> 6, w = hw & 63;
        int ki = kpt / 3, kj = kpt - ki * 3;
        float offy = g_offset[((size_t)b * 18 + 2 * kpt) * HWW + hw];
        float offx = g_offset[((size_t)b * 18 + 2 * kpt + 1) * HWW + hw];
        float py = (float)(h - 2 + 2 * ki) + offy;
        float pxx = (float)(w - 2 + 2 * kj) + offx;
        float fy0 = floorf(py), fx0 = floorf(pxx);
        int y0 = (int)fy0, x0 = (int)fx0;
        int y1 = y0 + 1, x1 = x0 + 1;
        float wy1 = py - fy0, wx1 = pxx - fx0;
        float wy0 = 1.f - wy1, wx0 = 1.f - wx1;
        bool vy0 = (unsigned)y0 < 64u, vy1 = (unsigned)y1 < 64u;
        bool vx0 = (unsigned)x0 < 64u, vx1 = (unsigned)x1 < 64u;
        float w00 = (vy0 && vx0) ? wy0 * wx0 : 0.f;
        float w01 = (vy0 && vx1) ? wy0 * wx1 : 0.f;
        float w10 = (vy1 && vx0) ? wy1 * wx0 : 0.f;
        float w11 = (vy1 && vx1) ? wy1 * wx1 : 0.f;
        int yc0 = min(max(y0, 0), 63), yc1 = min(max(y1, 0), 63);
        int xc0 = min(max(x0, 0), 63), xc1 = min(max(x1, 0), 63);
        int gb = b << 12;
        wts[kpt][px] = make_float4(w00, w01, w10, w11);
        idxs[kpt][px] = make_int4(gb + (yc0 << 6) + xc0, gb + (yc0 << 6) + xc1,
                                  gb + (yc1 << 6) + xc0, gb + (yc1 << 6) + xc1);
    }
    __syncthreads();

    int wid = threadIdx.x >> 5, lane = threadIdx.x & 31;
    int c8 = lane * 8;
    unsigned short* colbase = reinterpret_cast<unsigned short*>(g_colb);

    for (int task = wid; task < 288; task += 8) {
        int kpt = task >> 5, px = task & 31;
        float4 wv = wts[kpt][px];
        int4 iv = idxs[kpt][px];
        uint4 u00 = *reinterpret_cast<const uint4*>(g_xpm + (size_t)iv.x * CC + c8);
        uint4 u01 = *reinterpret_cast<const uint4*>(g_xpm + (size_t)iv.y * CC + c8);
        uint4 u10 = *reinterpret_cast<const uint4*>(g_xpm + (size_t)iv.z * CC + c8);
        uint4 u11 = *reinterpret_cast<const uint4*>(g_xpm + (size_t)iv.w * CC + c8);
        const __half2* h00 = reinterpret_cast<const __half2*>(&u00);
        const __half2* h01 = reinterpret_cast<const __half2*>(&u01);
        const __half2* h10 = reinterpret_cast<const __half2*>(&u10);
        const __half2* h11 = reinterpret_cast<const __half2*>(&u11);
        __align__(16) unsigned short his[8];
#pragma unroll
        for (int q = 0; q < 4; q++) {
            float2 a = __half22float2(h00[q]);
            float2 bq = __half22float2(h01[q]);
            float2 c = __half22float2(h10[q]);
            float2 d = __half22float2(h11[q]);
            float v0 = wv.x * a.x + wv.y * bq.x + wv.z * c.x + wv.w * d.x;
            float v1 = wv.x * a.y + wv.y * bq.y + wv.z * c.y + wv.w * d.y;
            his[q * 2] = f2h(v0);
            his[q * 2 + 1] = f2h(v1);
        }
        unsigned short* row = colbase + (size_t)(n0 + px) * COLROW + kpt * 256;
        *reinterpret_cast<uint4*>(row + c8) = *reinterpret_cast<const uint4*>(his);
    }
}

// ---------------- bn finalize: sums -> scale/shift (1 block) -----------------
__global__ void k_bnfin(const float* __restrict__ gamma, const float* __restrict__ beta,
                        int sel) {
    int ch = threadIdx.x;
    float s = sel ? g_bnsum2[ch] : g_bnsum1[ch];
    float q = sel ? g_bnsq2[ch] : g_bnsq1[ch];
    float mean = s * (1.f / FNN);
    float var = fmaxf(q * (1.f / FNN) - mean * mean, 0.f);
    float inv = rsqrtf(var + EPSB);
    float sc = inv * gamma[ch];
    if (sel) { g_scale2[ch] = sc; g_shift2[ch] = beta[ch] - mean * sc; }
    else     { g_scale1[ch] = sc; g_shift1[ch] = beta[ch] - mean * sc; }
}

// ---------------- convert1: out1 -> pixel-major fp16 (BN1+ReLU) -------------
__global__ __launch_bounds__(256)
void k_convert1() {
    __shared__ float t[64][33];
    __shared__ float sS[256], sH[256];
    int px0 = blockIdx.x * 32;
    int tid = threadIdx.x;
    int lane = tid & 31, wy = tid >> 5;
    for (int i = tid; i < 256; i += 256) { sS[i] = g_scale1[i]; sH[i] = g_shift1[i]; }
    __syncthreads();

    unsigned short* ob = reinterpret_cast<unsigned short*>(g_out1b);
    for (int c0 = 0; c0 < 256; c0 += 64) {
#pragma unroll
        for (int j = 0; j < 8; j++) {
            int cc = wy * 8 + j;
            t[cc][lane] = g_out1[(size_t)(c0 + cc) * NN + px0 + lane];
        }
        __syncthreads();
        int px = tid >> 3, g = tid & 7;
        __align__(16) unsigned short his[8];
#pragma unroll
        for (int j = 0; j < 8; j++) {
            int cc = g * 8 + j;
            float v = fmaxf(fmaf(t[cc][px], sS[c0 + cc], sH[c0 + cc]), 0.f);
            his[j] = f2h(v);
        }
        unsigned short* row = ob + (size_t)(px0 + px) * O1ROW;
        *reinterpret_cast<uint4*>(row + c0 + g * 8) = *reinterpret_cast<const uint4*>(his);
        __syncthreads();
    }
}

// ---------------- mma.sync fp16 GEMM, 128x256, K=2304, 4-stage, fused BN ----
__global__ __launch_bounds__(256, 1)
void k_gemm_mma(int wsel, const float* __restrict__ bias, int outsel, int implicitB) {
    extern __shared__ char smem[];
    uint32_t sb = smem_u32(smem);
    int tid = threadIdx.x;
    int m0 = blockIdx.x * 128;
    int n0 = blockIdx.y * 256;

    const __half* Ag = wsel ? g_wA2 : g_wA1;
    float* Cg = outsel ? g_out2 : g_out1;
    float* bns = outsel ? g_bnsum2 : g_bnsum1;
    float* bnq = outsel ? g_bnsq2 : g_bnsq1;
    const char* Abase = reinterpret_cast<const char*>(Ag) + (size_t)m0 * (CKK * 2);
    const char* Bbase = reinterpret_cast<const char*>(g_colb) + (size_t)n0 * (COLROW * 2);
    const char* Obase = reinterpret_cast<const char*>(g_out1b);

    auto load_stage = [&](int kc, int s) {
        uint32_t st = sb + s * STAGE_SZ;
        size_t kb = (size_t)kc * 128;
        int kpt = kc >> 2, part = kc & 3;
        uint32_t srcoff = ((uint32_t)part) << 7;
        if (!implicitB) {
#pragma unroll
            for (int i = 0; i < 12; i++) {
                int idx = tid + i * 256;
                if (idx < 1024) {
                    int r = idx >> 3, c = idx & 7;
                    uint32_t off = SWZ128(r * 128 + c * 16);
                    CP_ASYNC16(st + off, Abase + (size_t)r * (CKK * 2) + kb + c * 16);
                } else {
                    int j = idx - 1024;
                    int r = j >> 3, c = j & 7;
                    uint32_t off = SWZ128(r * 128 + c * 16);
                    CP_ASYNC16(st + 16384 + off,
                               Bbase + (size_t)r * (COLROW * 2) + kpt * 512 + srcoff + c * 16);
                }
            }
        } else {
            int ki = kpt / 3, kj = kpt - 3 * ki;
            int dn = (ki - 1) * 64 + (kj - 1);
#pragma unroll
            for (int i = 0; i < 12; i++) {
                int idx = tid + i * 256;
                if (idx < 1024) {
                    int r = idx >> 3, c = idx & 7;
                    uint32_t off = SWZ128(r * 128 + c * 16);
                    CP_ASYNC16(st + off, Abase + (size_t)r * (CKK * 2) + kb + c * 16);
                } else {
                    int j = idx - 1024;
                    int r = j >> 3, c = j & 7;
                    int n = n0 + r;
                    int h = (n >> 6) & 63, w = n & 63;
                    int y = h - 1 + ki, xw = w - 1 + kj;
                    bool valid = ((unsigned)y < 64u) && ((unsigned)xw < 64u);
                    int np = valid ? n + dn : 0;
                    uint32_t sz = valid ? 16u : 0u;
                    uint32_t off = SWZ128(r * 128 + c * 16);
                    CP_ASYNC16Z(st + 16384 + off,
                                Obase + (size_t)np * 512 + srcoff + c * 16, sz);
                }
            }
        }
        CP_COMMIT();
    };

    int lane = tid & 31, w = tid >> 5;
    int wm = w >> 1, wn = w & 1;
    int mW = wm * 32, nW = wn * 128;
    int gq = lane >> 3, rr = lane & 7;
    int rowin = (gq & 1) * 8 + rr;
    int kboff = (gq >> 1) * 16;

    float acc[2][16][4];
#pragma unroll
    for (int mt = 0; mt < 2; mt++)
#pragma unroll
        for (int j = 0; j < 16; j++)
#pragma unroll
            for (int q = 0; q < 4; q++) acc[mt][j][q] = 0.f;

    uint32_t aOff[2], aXor[2], bOff[8], bXor[8];
#pragma unroll
    for (int mt = 0; mt < 2; mt++) {
        int row = mW + mt * 16 + rowin;
        aOff[mt] = row * 128;
        aXor[mt] = (row & 7) << 4;
    }
#pragma unroll
    for (int nt = 0; nt < 8; nt++) {
        int row = nW + nt * 16 + rowin;
        bOff[nt] = row * 128;
        bXor[nt] = (row & 7) << 4;
    }

    load_stage(0, 0);
    load_stage(1, 1);
    load_stage(2, 2);

    for (int k = 0; k < NUM_KCH; k++) {
        int s = k & 3;
        uint32_t stA = sb + s * STAGE_SZ;
        uint32_t stB = stA + 16384;
        CP_WAIT2();
        __syncthreads();
        if (k + 3 < NUM_KCH) load_stage(k + 3, (k + 3) & 3);
        else CP_COMMIT();

#pragma unroll
        for (int ks = 0; ks < 4; ks++) {
            uint32_t kb = ks * 32 + kboff;
            uint32_t af[2][4];
#pragma unroll
            for (int mt = 0; mt < 2; mt++)
                LDSM4(af[mt][0], af[mt][1], af[mt][2], af[mt][3],
                      stA + aOff[mt] + (kb ^ aXor[mt]));
#pragma unroll
            for (int nt = 0; nt < 8; nt++) {
                uint32_t bf0, bf1, bf2, bf3;
                LDSM4(bf0, bf1, bf2, bf3, stB + bOff[nt] + (kb ^ bXor[nt]));
#pragma unroll
                for (int mt = 0; mt < 2; mt++) {
                    MMA16816F16(acc[mt][nt * 2], af[mt][0], af[mt][1], af[mt][2], af[mt][3],
                                bf0, bf2);
                    MMA16816F16(acc[mt][nt * 2 + 1], af[mt][0], af[mt][1], af[mt][2], af[mt][3],
                                bf1, bf3);
                }
            }
        }
    }

    int qr = lane >> 2;
    int qc = (lane & 3) * 2;
#pragma unroll
    for (int mt = 0; mt < 2; mt++) {
        int row0 = m0 + mW + mt * 16 + qr;
        float bv0 = bias ? bias[row0] : 0.f;
        float bv1 = bias ? bias[row0 + 8] : 0.f;
        float s0 = 0.f, q0 = 0.f, s1 = 0.f, q1 = 0.f;
#pragma unroll
        for (int j = 0; j < 16; j++) {
            int col = n0 + nW + j * 8 + qc;
            float2 v0 = make_float2(acc[mt][j][0] + bv0, acc[mt][j][1] + bv0);
            float2 v1 = make_float2(acc[mt][j][2] + bv1, acc[mt][j][3] + bv1);
            s0 += v0.x + v0.y;
            q0 = fmaf(v0.x, v0.x, fmaf(v0.y, v0.y, q0));
            s1 += v1.x + v1.y;
            q1 = fmaf(v1.x, v1.x, fmaf(v1.y, v1.y, q1));
            *reinterpret_cast<float2*>(Cg + (size_t)row0 * NN + col) = v0;
            *reinterpret_cast<float2*>(Cg + (size_t)(row0 + 8) * NN + col) = v1;
        }
        s0 += __shfl_xor_sync(0xffffffff, s0, 1);
        s0 += __shfl_xor_sync(0xffffffff, s0, 2);
        q0 += __shfl_xor_sync(0xffffffff, q0, 1);
        q0 += __shfl_xor_sync(0xffffffff, q0, 2);
        s1 += __shfl_xor_sync(0xffffffff, s1, 1);
        s1 += __shfl_xor_sync(0xffffffff, s1, 2);
        q1 += __shfl_xor_sync(0xffffffff, q1, 1);
        q1 += __shfl_xor_sync(0xffffffff, q1, 2);
        if ((lane & 3) == 0) {
            atomicAdd(&bns[row0], s0);
            atomicAdd(&bnq[row0], q0);
            atomicAdd(&bns[row0 + 8], s1);
            atomicAdd(&bnq[row0 + 8], q1);
        }
    }
}

// ---------------- final: relu(bn2(out2) + x) in NCHW ------------------------
__global__ __launch_bounds__(256)
void k_final(const float* __restrict__ x, float* __restrict__ out) {
    int i = blockIdx.x * 256 + threadIdx.x;
    int hw = i & 4095;
    int o = (i >> 12) & 255;
    int b = i >> 20;
    float v = fmaf(g_out2[(size_t)o * NN + b * HWW + hw], g_scale2[o], g_shift2[o]) + x[i];
    out[i] = fmaxf(v, 0.f);
}

// ---------------- launch -----------------------------------------------------
extern "C" void kernel_launch(void* const* d_in, const int* in_sizes, int n_in,
                              void* d_out, int out_size) {
    const float* x     = (const float*)d_in[0];
    const float* off_w = (const float*)d_in[1];
    const float* off_b = (const float*)d_in[2];
    const float* dw    = (const float*)d_in[3];
    const float* db    = (const float*)d_in[4];
    const float* bn1_g = (const float*)d_in[5];
    const float* bn1_b = (const float*)d_in[6];
    const float* w2    = (const float*)d_in[7];
    const float* bn2_g = (const float*)d_in[8];
    const float* bn2_b = (const float*)d_in[9];
    float* out = (float*)d_out;

    cudaFuncSetAttribute(k_gemm_mma, cudaFuncAttributeMaxDynamicSharedMemorySize, GEMM_SMEM);
    cudaFuncSetAttribute(k_gemm_off, cudaFuncAttributeMaxDynamicSharedMemorySize, OFF_SMEM);

    k_zero<<<1, 256>>>();
    k_transpose_x<<<dim3(NN / 32, 4), 256>>>(x);
    k_wprep<<<dim3(OO, 3), 256>>>(dw, w2, off_w);
    k_gemm_off<<<NN / 64, 256, OFF_SMEM>>>(off_b);
    k_im2col_deform<<<NN / 32, 256>>>();
    k_gemm_mma<<<dim3(2, 64), 256, GEMM_SMEM>>>(0, db, 0, 0);
    k_bnfin<<<1, 256>>>(bn1_g, bn1_b, 0);
    k_convert1<<<NN / 32, 256>>>();
    k_gemm_mma<<<dim3(2, 64), 256, GEMM_SMEM>>>(1, nullptr, 1, 1);
    k_bnfin<<<1, 256>>>(bn2_g, bn2_b, 1);
    k_final<<<(BB * OO * HWW + 255) / 256, 256>>>(x, out);
}

// round 17
// speedup vs baseline: 1.0010x; 1.0010x over previous
#include <cuda_runtime.h>
#include <cuda_fp16.h>
#include <cstdint>

#define BB 4
#define CC 256
#define OO 256
#define HWW 4096
#define NN 16384          // BB*HWW
#define CKK 2304          // CC*9 — plain fp16 K
#define EPSB 1e-5f
#define FNN 16384.0f

#define NSTAGE 3
#define STAGE_SZ 49152      // A 16KB + B 32KB per stage (main GEMM)
#define GEMM_SMEM (NSTAGE * STAGE_SZ)      // 144 KB
#define NUM_KCH 36          // CKK*2 bytes / 128B per chunk

#define OFF_STAGE 12288     // A 4KB (32 rows) + B 8KB (64 rows)
#define OFF_SMEM (NSTAGE * OFF_STAGE)      // 36 KB
#define OFF_KCH 9           // chunks per K-split

#define COLROW 2304         // per pixel: 9 kpt x 256 fp16
#define O1ROW 256           // per pixel: 256 fp16

// ---------------- scratch (device globals; no allocs allowed) ----------------
__device__ float g_offset[BB * 18 * HWW];                       // 4.7 MB
__device__ __half g_xpm[(size_t)NN * CC];                       // 8.4 MB NHWC fp16 x
__device__ __half g_colb[(size_t)NN * COLROW];                  // 75.5 MB
__device__ __half g_wA1[(size_t)OO * CKK];                      // 1.2 MB [m][k]
__device__ __half g_wA2[(size_t)OO * CKK];
__device__ __half g_wOff[32 * CKK];                             // 147 KB (18 pad 32)
__device__ float g_out1[(size_t)OO * NN];                       // 16.8 MB [o][n]
__device__ float g_out2[(size_t)OO * NN];
__device__ __half g_out1b[(size_t)NN * O1ROW];                  // 8.4 MB
__device__ float g_scale1[OO], g_shift1[OO], g_scale2[OO], g_shift2[OO];
__device__ float g_bnsum1[OO], g_bnsq1[OO], g_bnsum2[OO], g_bnsq2[OO];

// ---------------- helpers ----------------------------------------------------
__device__ __forceinline__ uint32_t smem_u32(const void* p) {
    uint32_t a;
    asm("{ .reg .u64 t; cvta.to.shared.u64 t, %1; cvt.u32.u64 %0, t; }" : "=r"(a) : "l"(p));
    return a;
}
#define SWZ128(o) ((o) ^ (((o) >> 3) & 0x70))
#define CP_ASYNC16(dst, src) \
    asm volatile("cp.async.cg.shared.global [%0], [%1], 16;" :: "r"(dst), "l"(src))
#define CP_ASYNC16Z(dst, src, sz) \
    asm volatile("cp.async.cg.shared.global [%0], [%1], 16, %2;" :: "r"(dst), "l"(src), "r"(sz))
#define CP_COMMIT() asm volatile("cp.async.commit_group;" ::: "memory")
#define CP_WAIT2()  asm volatile("cp.async.wait_group 2;" ::: "memory")

#define LDSM4(r0, r1, r2, r3, addr) \
    asm volatile("ldmatrix.sync.aligned.m8n8.x4.shared.b16 {%0,%1,%2,%3}, [%4];" \
                 : "=r"(r0), "=r"(r1), "=r"(r2), "=r"(r3) : "r"(addr))

#define MMA16816F16(d, a0, a1, a2, a3, b0, b1) \
    asm volatile("mma.sync.aligned.m16n8k16.row.col.f32.f16.f16.f32 " \
                 "{%0,%1,%2,%3},{%4,%5,%6,%7},{%8,%9},{%0,%1,%2,%3};" \
                 : "+f"((d)[0]), "+f"((d)[1]), "+f"((d)[2]), "+f"((d)[3]) \
                 : "r"(a0), "r"(a1), "r"(a2), "r"(a3), "r"(b0), "r"(b1))

__device__ __forceinline__ unsigned short f2h(float v) {
    __half h = __float2half_rn(v);
    return *reinterpret_cast<unsigned short*>(&h);
}

// ---------------- zero: g_offset + bn sums ------------------------------------
__global__ void k_zero() {
    int i = blockIdx.x * 256 + threadIdx.x;
    if (i < BB * 18 * HWW) g_offset[i] = 0.f;
    if (i < OO) { g_bnsum1[i] = 0.f; g_bnsq1[i] = 0.f; g_bnsum2[i] = 0.f; g_bnsq2[i] = 0.f; }
}

// ---------------- transpose x: NCHW fp32 -> NHWC fp16 (g_xpm) ---------------
__global__ __launch_bounds__(256)
void k_transpose_x(const float* __restrict__ x) {
    __shared__ float t[64][33];
    int n0 = blockIdx.x * 32;
    int c0 = blockIdx.y * 64;
    int b = n0 >> 12;
    int hw0 = n0 & 4095;
    int lane = threadIdx.x & 31, wy = threadIdx.x >> 5;
#pragma unroll
    for (int j = 0; j < 8; j++) {
        int cc = wy * 8 + j;
        t[cc][lane] = x[((size_t)b * CC + c0 + cc) * HWW + hw0 + lane];
    }
    __syncthreads();
#pragma unroll
    for (int j = 0; j < 4; j++) {
        int px = wy * 4 + j;
        __half2 h = __floats2half2_rn(t[lane * 2][px], t[lane * 2 + 1][px]);
        *reinterpret_cast<__half2*>(g_xpm + (size_t)(n0 + px) * CC + c0 + lane * 2) = h;
    }
}

// ---------------- weight prep: one block per m row, coalesced writes ---------
__global__ __launch_bounds__(256)
void k_wprep(const float* __restrict__ dw, const float* __restrict__ w2,
             const float* __restrict__ off_w) {
    __shared__ float sw[CKK];
    int m = blockIdx.x;
    int y = blockIdx.y;
    if (y == 2 && m >= 32) return;
    bool zero = (y == 2 && m >= 18);
    const float* src = (y == 0) ? dw : (y == 1 ? w2 : off_w);
    __half* dst = (y == 0) ? g_wA1 : (y == 1 ? g_wA2 : g_wOff);
    int tid = threadIdx.x;
    if (!zero) {
        for (int i = tid; i < CKK; i += 256) sw[i] = src[(size_t)m * CKK + i];
    }
    __syncthreads();
    unsigned short* drow = reinterpret_cast<unsigned short*>(dst) + (size_t)m * CKK;
#pragma unroll
    for (int kpt = 0; kpt < 9; kpt++) {
        unsigned short v = zero ? (unsigned short)0 : f2h(sw[tid * 9 + kpt]);
        drow[kpt * 256 + tid] = v;
    }
}

// ---------------- offset conv GEMM, K-split x4: [18(32)x2304]@[2304xNN] -----
// grid (256, 4): x = 64-pixel n-tile, y = K quarter (9 chunks). atomicAdd out.
__global__ __launch_bounds__(256, 3)
void k_gemm_off(const float* __restrict__ off_b) {
    extern __shared__ char smem[];
    uint32_t sb = smem_u32(smem);
    int tid = threadIdx.x;
    int n0 = blockIdx.x * 64;
    int kbase = blockIdx.y * OFF_KCH;
    int b = n0 >> 12;

    const char* Abase = reinterpret_cast<const char*>(g_wOff);
    const char* Xbase = reinterpret_cast<const char*>(g_xpm);

    auto load_stage = [&](int kc, int s) {
        uint32_t st = sb + s * OFF_STAGE;
        int kpt = kc >> 2, part = kc & 3;
        uint32_t srcoff = ((uint32_t)part) << 7;
        int ki = kpt / 3, kj = kpt - 3 * ki;
        int dn = (ki - 1) * 128 + (kj - 1) * 2;   // dil=2 shifts
#pragma unroll
        for (int i = 0; i < 3; i++) {
            int idx = tid + i * 256;
            if (idx < 256) {
                int r = idx >> 3, c = idx & 7;
                uint32_t off = SWZ128(r * 128 + c * 16);
                CP_ASYNC16(st + off, Abase + (size_t)r * (CKK * 2) + (size_t)kc * 128 + c * 16);
            } else {
                int j = idx - 256;
                int r = j >> 3, c = j & 7;
                int n = n0 + r;
                int h = (n >> 6) & 63, w = n & 63;
                int y = h - 2 + 2 * ki, xw = w - 2 + 2 * kj;
                bool valid = ((unsigned)y < 64u) && ((unsigned)xw < 64u);
                int np = valid ? n + dn : 0;
                uint32_t sz = valid ? 16u : 0u;
                uint32_t off = SWZ128(r * 128 + c * 16);
                CP_ASYNC16Z(st + 4096 + off, Xbase + (size_t)np * 512 + srcoff + c * 16, sz);
            }
        }
        CP_COMMIT();
    };

    int lane = tid & 31, w = tid >> 5;
    int wm = w >> 2, wn = w & 3;      // 2m x 4n warp grid
    int mW = wm * 16, nW = wn * 16;
    int gq = lane >> 3, rr = lane & 7;
    int rowin = (gq & 1) * 8 + rr;
    int kboff = (gq >> 1) * 16;

    float acc[2][4];
#pragma unroll
    for (int j = 0; j < 2; j++)
#pragma unroll
        for (int q = 0; q < 4; q++) acc[j][q] = 0.f;

    uint32_t aOff = (mW + rowin) * 128;
    uint32_t aXor = ((mW + rowin) & 7) << 4;
    uint32_t bOff = (nW + rowin) * 128;
    uint32_t bXor = ((nW + rowin) & 7) << 4;

    load_stage(kbase + 0, 0);
    load_stage(kbase + 1, 1);
    load_stage(kbase + 2, 2);

    for (int kk = 0; kk < OFF_KCH; kk++) {
        int s = kk % NSTAGE;
        uint32_t stA = sb + s * OFF_STAGE;
        uint32_t stB = stA + 4096;
        CP_WAIT2();
        __syncthreads();

#pragma unroll
        for (int ks = 0; ks < 4; ks++) {
            uint32_t kb = ks * 32 + kboff;
            uint32_t a0, a1, a2, a3;
            LDSM4(a0, a1, a2, a3, stA + aOff + (kb ^ aXor));
            uint32_t bf0, bf1, bf2, bf3;
            LDSM4(bf0, bf1, bf2, bf3, stB + bOff + (kb ^ bXor));
            MMA16816F16(acc[0], a0, a1, a2, a3, bf0, bf2);
            MMA16816F16(acc[1], a0, a1, a2, a3, bf1, bf3);
        }
        __syncthreads();
        if (kk + 3 < OFF_KCH) load_stage(kbase + kk + 3, s);
        else CP_COMMIT();
    }

    // epilogue: atomicAdd rows < 18 into g_offset (+off_b from split 0)
    int qr = lane >> 2;
    int qc = (lane & 3) * 2;
    int hw0 = (n0 & 4095) + nW + qc;
    int rowA = mW + qr;
    int rowB = rowA + 8;
    bool addb = (blockIdx.y == 0);
#pragma unroll
    for (int j = 0; j < 2; j++) {
        int hw = hw0 + j * 8;
        if (rowA < 18) {
            float bv = addb ? off_b[rowA] : 0.f;
            float* p = g_offset + (size_t)(b * 18 + rowA) * HWW + hw;
            atomicAdd(p, acc[j][0] + bv);
            atomicAdd(p + 1, acc[j][1] + bv);
        }
        if (rowB < 18) {
            float bv = addb ? off_b[rowB] : 0.f;
            float* p = g_offset + (size_t)(b * 18 + rowB) * HWW + hw;
            atomicAdd(p, acc[j][2] + bv);
            atomicAdd(p + 1, acc[j][3] + bv);
        }
    }
}

// ---------------- deformable im2col: NHWC fp16 gather -----------------------
__global__ __launch_bounds__(256)
void k_im2col_deform() {
    __shared__ float4 wts[9][32];
    __shared__ int4 idxs[9][32];

    int n0 = blockIdx.x * 32;
    int b = n0 >> 12;

    for (int t = threadIdx.x; t < 288; t += 256) {
        int kpt = t >> 5, px = t & 31;
        int n = n0 + px;
        int hw = n & 4095;
        int h = hw >> 6, w = hw & 63;
        int ki = kpt / 3, kj = kpt - ki * 3;
        float offy = g_offset[((size_t)b * 18 + 2 * kpt) * HWW + hw];
        float offx = g_offset[((size_t)b * 18 + 2 * kpt + 1) * HWW + hw];
        float py = (float)(h - 2 + 2 * ki) + offy;
        float pxx = (float)(w - 2 + 2 * kj) + offx;
        float fy0 = floorf(py), fx0 = floorf(pxx);
        int y0 = (int)fy0, x0 = (int)fx0;
        int y1 = y0 + 1, x1 = x0 + 1;
        float wy1 = py - fy0, wx1 = pxx - fx0;
        float wy0 = 1.f - wy1, wx0 = 1.f - wx1;
        bool vy0 = (unsigned)y0 < 64u, vy1 = (unsigned)y1 < 64u;
        bool vx0 = (unsigned)x0 < 64u, vx1 = (unsigned)x1 < 64u;
        float w00 = (vy0 && vx0) ? wy0 * wx0 : 0.f;
        float w01 = (vy0 && vx1) ? wy0 * wx1 : 0.f;
        float w10 = (vy1 && vx0) ? wy1 * wx0 : 0.f;
        float w11 = (vy1 && vx1) ? wy1 * wx1 : 0.f;
        int yc0 = min(max(y0, 0), 63), yc1 = min(max(y1, 0), 63);
        int xc0 = min(max(x0, 0), 63), xc1 = min(max(x1, 0), 63);
        int gb = b << 12;
        wts[kpt][px] = make_float4(w00, w01, w10, w11);
        idxs[kpt][px] = make_int4(gb + (yc0 << 6) + xc0, gb + (yc0 << 6) + xc1,
                                  gb + (yc1 << 6) + xc0, gb + (yc1 << 6) + xc1);
    }
    __syncthreads();

    int wid = threadIdx.x >> 5, lane = threadIdx.x & 31;
    int c8 = lane * 8;
    unsigned short* colbase = reinterpret_cast<unsigned short*>(g_colb);

    for (int task = wid; task < 288; task += 8) {
        int kpt = task >> 5, px = task & 31;
        float4 wv = wts[kpt][px];
        int4 iv = idxs[kpt][px];
        uint4 u00 = *reinterpret_cast<const uint4*>(g_xpm + (size_t)iv.x * CC + c8);
        uint4 u01 = *reinterpret_cast<const uint4*>(g_xpm + (size_t)iv.y * CC + c8);
        uint4 u10 = *reinterpret_cast<const uint4*>(g_xpm + (size_t)iv.z * CC + c8);
        uint4 u11 = *reinterpret_cast<const uint4*>(g_xpm + (size_t)iv.w * CC + c8);
        const __half2* h00 = reinterpret_cast<const __half2*>(&u00);
        const __half2* h01 = reinterpret_cast<const __half2*>(&u01);
        const __half2* h10 = reinterpret_cast<const __half2*>(&u10);
        const __half2* h11 = reinterpret_cast<const __half2*>(&u11);
        __align__(16) unsigned short his[8];
#pragma unroll
        for (int q = 0; q < 4; q++) {
            float2 a = __half22float2(h00[q]);
            float2 bq = __half22float2(h01[q]);
            float2 c = __half22float2(h10[q]);
            float2 d = __half22float2(h11[q]);
            float v0 = wv.x * a.x + wv.y * bq.x + wv.z * c.x + wv.w * d.x;
            float v1 = wv.x * a.y + wv.y * bq.y + wv.z * c.y + wv.w * d.y;
            his[q * 2] = f2h(v0);
            his[q * 2 + 1] = f2h(v1);
        }
        unsigned short* row = colbase + (size_t)(n0 + px) * COLROW + kpt * 256;
        *reinterpret_cast<uint4*>(row + c8) = *reinterpret_cast<const uint4*>(his);
    }
}

// ---------------- bn finalize: sums -> scale/shift (1 block) -----------------
__global__ void k_bnfin(const float* __restrict__ gamma, const float* __restrict__ beta,
                        int sel) {
    int ch = threadIdx.x;
    float s = sel ? g_bnsum2[ch] : g_bnsum1[ch];
    float q = sel ? g_bnsq2[ch] : g_bnsq1[ch];
    float mean = s * (1.f / FNN);
    float var = fmaxf(q * (1.f / FNN) - mean * mean, 0.f);
    float inv = rsqrtf(var + EPSB);
    float sc = inv * gamma[ch];
    if (sel) { g_scale2[ch] = sc; g_shift2[ch] = beta[ch] - mean * sc; }
    else     { g_scale1[ch] = sc; g_shift1[ch] = beta[ch] - mean * sc; }
}

// ---------------- convert1: out1 -> pixel-major fp16 (BN1+ReLU) -------------
__global__ __launch_bounds__(256)
void k_convert1() {
    __shared__ float t[64][33];
    __shared__ float sS[256], sH[256];
    int px0 = blockIdx.x * 32;
    int tid = threadIdx.x;
    int lane = tid & 31, wy = tid >> 5;
    for (int i = tid; i < 256; i += 256) { sS[i] = g_scale1[i]; sH[i] = g_shift1[i]; }
    __syncthreads();

    unsigned short* ob = reinterpret_cast<unsigned short*>(g_out1b);
    for (int c0 = 0; c0 < 256; c0 += 64) {
#pragma unroll
        for (int j = 0; j < 8; j++) {
            int cc = wy * 8 + j;
            t[cc][lane] = g_out1[(size_t)(c0 + cc) * NN + px0 + lane];
        }
        __syncthreads();
        int px = tid >> 3, g = tid & 7;
        __align__(16) unsigned short his[8];
#pragma unroll
        for (int j = 0; j < 8; j++) {
            int cc = g * 8 + j;
            float v = fmaxf(fmaf(t[cc][px], sS[c0 + cc], sH[c0 + cc]), 0.f);
            his[j] = f2h(v);
        }
        unsigned short* row = ob + (size_t)(px0 + px) * O1ROW;
        *reinterpret_cast<uint4*>(row + c0 + g * 8) = *reinterpret_cast<const uint4*>(his);
        __syncthreads();
    }
}

// ---------------- mma.sync fp16 GEMM, 128x256, K=2304, fused BN stats -------
__global__ __launch_bounds__(256, 1)
void k_gemm_mma(int wsel, const float* __restrict__ bias, int outsel, int implicitB) {
    extern __shared__ char smem[];
    uint32_t sb = smem_u32(smem);
    int tid = threadIdx.x;
    int m0 = blockIdx.x * 128;
    int n0 = blockIdx.y * 256;

    const __half* Ag = wsel ? g_wA2 : g_wA1;
    float* Cg = outsel ? g_out2 : g_out1;
    float* bns = outsel ? g_bnsum2 : g_bnsum1;
    float* bnq = outsel ? g_bnsq2 : g_bnsq1;
    const char* Abase = reinterpret_cast<const char*>(Ag) + (size_t)m0 * (CKK * 2);
    const char* Bbase = reinterpret_cast<const char*>(g_colb) + (size_t)n0 * (COLROW * 2);
    const char* Obase = reinterpret_cast<const char*>(g_out1b);

    auto load_stage = [&](int kc, int s) {
        uint32_t st = sb + s * STAGE_SZ;
        size_t kb = (size_t)kc * 128;
        int kpt = kc >> 2, part = kc & 3;
        uint32_t srcoff = ((uint32_t)part) << 7;
        if (!implicitB) {
#pragma unroll
            for (int i = 0; i < 12; i++) {
                int idx = tid + i * 256;
                if (idx < 1024) {
                    int r = idx >> 3, c = idx & 7;
                    uint32_t off = SWZ128(r * 128 + c * 16);
                    CP_ASYNC16(st + off, Abase + (size_t)r * (CKK * 2) + kb + c * 16);
                } else {
                    int j = idx - 1024;
                    int r = j >> 3, c = j & 7;
                    uint32_t off = SWZ128(r * 128 + c * 16);
                    CP_ASYNC16(st + 16384 + off,
                               Bbase + (size_t)r * (COLROW * 2) + kpt * 512 + srcoff + c * 16);
                }
            }
        } else {
            int ki = kpt / 3, kj = kpt - 3 * ki;
            int dn = (ki - 1) * 64 + (kj - 1);
#pragma unroll
            for (int i = 0; i < 12; i++) {
                int idx = tid + i * 256;
                if (idx < 1024) {
                    int r = idx >> 3, c = idx & 7;
                    uint32_t off = SWZ128(r * 128 + c * 16);
                    CP_ASYNC16(st + off, Abase + (size_t)r * (CKK * 2) + kb + c * 16);
                } else {
                    int j = idx - 1024;
                    int r = j >> 3, c = j & 7;
                    int n = n0 + r;
                    int h = (n >> 6) & 63, w = n & 63;
                    int y = h - 1 + ki, xw = w - 1 + kj;
                    bool valid = ((unsigned)y < 64u) && ((unsigned)xw < 64u);
                    int np = valid ? n + dn : 0;
                    uint32_t sz = valid ? 16u : 0u;
                    uint32_t off = SWZ128(r * 128 + c * 16);
                    CP_ASYNC16Z(st + 16384 + off,
                                Obase + (size_t)np * 512 + srcoff + c * 16, sz);
                }
            }
        }
        CP_COMMIT();
    };

    int lane = tid & 31, w = tid >> 5;
    int wm = w >> 1, wn = w & 1;
    int mW = wm * 32, nW = wn * 128;
    int gq = lane >> 3, rr = lane & 7;
    int rowin = (gq & 1) * 8 + rr;
    int kboff = (gq >> 1) * 16;

    float acc[2][16][4];
#pragma unroll
    for (int mt = 0; mt < 2; mt++)
#pragma unroll
        for (int j = 0; j < 16; j++)
#pragma unroll
            for (int q = 0; q < 4; q++) acc[mt][j][q] = 0.f;

    uint32_t aOff[2], aXor[2], bOff[8], bXor[8];
#pragma unroll
    for (int mt = 0; mt < 2; mt++) {
        int row = mW + mt * 16 + rowin;
        aOff[mt] = row * 128;
        aXor[mt] = (row & 7) << 4;
    }
#pragma unroll
    for (int nt = 0; nt < 8; nt++) {
        int row = nW + nt * 16 + rowin;
        bOff[nt] = row * 128;
        bXor[nt] = (row & 7) << 4;
    }

    load_stage(0, 0);
    load_stage(1, 1);
    load_stage(2, 2);

    for (int k = 0; k < NUM_KCH; k++) {
        int s = k % NSTAGE;
        uint32_t stA = sb + s * STAGE_SZ;
        uint32_t stB = stA + 16384;
        CP_WAIT2();
        __syncthreads();

#pragma unroll
        for (int ks = 0; ks < 4; ks++) {
            uint32_t kb = ks * 32 + kboff;
            uint32_t af[2][4];
#pragma unroll
            for (int mt = 0; mt < 2; mt++)
                LDSM4(af[mt][0], af[mt][1], af[mt][2], af[mt][3],
                      stA + aOff[mt] + (kb ^ aXor[mt]));
#pragma unroll
            for (int nt = 0; nt < 8; nt++) {
                uint32_t bf0, bf1, bf2, bf3;
                LDSM4(bf0, bf1, bf2, bf3, stB + bOff[nt] + (kb ^ bXor[nt]));
#pragma unroll
                for (int mt = 0; mt < 2; mt++) {
                    MMA16816F16(acc[mt][nt * 2], af[mt][0], af[mt][1], af[mt][2], af[mt][3],
                                bf0, bf2);
                    MMA16816F16(acc[mt][nt * 2 + 1], af[mt][0], af[mt][1], af[mt][2], af[mt][3],
                                bf1, bf3);
                }
            }
        }
        __syncthreads();
        if (k + 3 < NUM_KCH) load_stage(k + 3, s);
        else CP_COMMIT();
    }

    int qr = lane >> 2;
    int qc = (lane & 3) * 2;
#pragma unroll
    for (int mt = 0; mt < 2; mt++) {
        int row0 = m0 + mW + mt * 16 + qr;
        float bv0 = bias ? bias[row0] : 0.f;
        float bv1 = bias ? bias[row0 + 8] : 0.f;
        float s0 = 0.f, q0 = 0.f, s1 = 0.f, q1 = 0.f;
#pragma unroll
        for (int j = 0; j < 16; j++) {
            int col = n0 + nW + j * 8 + qc;
            float2 v0 = make_float2(acc[mt][j][0] + bv0, acc[mt][j][1] + bv0);
            float2 v1 = make_float2(acc[mt][j][2] + bv1, acc[mt][j][3] + bv1);
            s0 += v0.x + v0.y;
            q0 = fmaf(v0.x, v0.x, fmaf(v0.y, v0.y, q0));
            s1 += v1.x + v1.y;
            q1 = fmaf(v1.x, v1.x, fmaf(v1.y, v1.y, q1));
            *reinterpret_cast<float2*>(Cg + (size_t)row0 * NN + col) = v0;
            *reinterpret_cast<float2*>(Cg + (size_t)(row0 + 8) * NN + col) = v1;
        }
        s0 += __shfl_xor_sync(0xffffffff, s0, 1);
        s0 += __shfl_xor_sync(0xffffffff, s0, 2);
        q0 += __shfl_xor_sync(0xffffffff, q0, 1);
        q0 += __shfl_xor_sync(0xffffffff, q0, 2);
        s1 += __shfl_xor_sync(0xffffffff, s1, 1);
        s1 += __shfl_xor_sync(0xffffffff, s1, 2);
        q1 += __shfl_xor_sync(0xffffffff, q1, 1);
        q1 += __shfl_xor_sync(0xffffffff, q1, 2);
        if ((lane & 3) == 0) {
            atomicAdd(&bns[row0], s0);
            atomicAdd(&bnq[row0], q0);
            atomicAdd(&bns[row0 + 8], s1);
            atomicAdd(&bnq[row0 + 8], q1);
        }
    }
}

// ---------------- final: relu(bn2(out2) + x) in NCHW ------------------------
__global__ __launch_bounds__(256)
void k_final(const float* __restrict__ x, float* __restrict__ out) {
    int i = blockIdx.x * 256 + threadIdx.x;
    int hw = i & 4095;
    int o = (i >> 12) & 255;
    int b = i >> 20;
    float v = fmaf(g_out2[(size_t)o * NN + b * HWW + hw], g_scale2[o], g_shift2[o]) + x[i];
    out[i] = fmaxf(v, 0.f);
}

// ---------------- launch -----------------------------------------------------
extern "C" void kernel_launch(void* const* d_in, const int* in_sizes, int n_in,
                              void* d_out, int out_size) {
    const float* x     = (const float*)d_in[0];
    const float* off_w = (const float*)d_in[1];
    const float* off_b = (const float*)d_in[2];
    const float* dw    = (const float*)d_in[3];
    const float* db    = (const float*)d_in[4];
    const float* bn1_g = (const float*)d_in[5];
    const float* bn1_b = (const float*)d_in[6];
    const float* w2    = (const float*)d_in[7];
    const float* bn2_g = (const float*)d_in[8];
    const float* bn2_b = (const float*)d_in[9];
    float* out = (float*)d_out;

    cudaFuncSetAttribute(k_gemm_mma, cudaFuncAttributeMaxDynamicSharedMemorySize, GEMM_SMEM);
    cudaFuncSetAttribute(k_gemm_off, cudaFuncAttributeMaxDynamicSharedMemorySize, OFF_SMEM);

    k_zero<<<(BB * 18 * HWW + 255) / 256, 256>>>();
    k_transpose_x<<<dim3(NN / 32, 4), 256>>>(x);
    k_wprep<<<dim3(OO, 3), 256>>>(dw, w2, off_w);
    k_gemm_off<<<dim3(NN / 64, 4), 256, OFF_SMEM>>>(off_b);
    k_im2col_deform<<<NN / 32, 256>>>();
    k_gemm_mma<<<dim3(2, 64), 256, GEMM_SMEM>>>(0, db, 0, 0);
    k_bnfin<<<1, 256>>>(bn1_g, bn1_b, 0);
    k_convert1<<<NN / 32, 256>>>();
    k_gemm_mma<<<dim3(2, 64), 256, GEMM_SMEM>>>(1, nullptr, 1, 1);
    k_bnfin<<<1, 256>>>(bn2_g, bn2_b, 1);
    k_final<<<(BB * OO * HWW + 255) / 256, 256>>>(x, out);
}